// round 15
// baseline (speedup 1.0000x reference)
#include <cuda_runtime.h>
#include <cuda_bf16.h>

// out[n, j] = x[n, j] + (1/512) * sum_{k=512..1023} x[n, k]
// x: [131072, 1024] f32, out: [131072, 512] f32
//
// FINAL kernel — best wall time over 14 rounds (114.75us, reproduced 4x in
// the 114.75-115.7 band). 256-thread block = 2 independent rows x 128
// threads, one __syncthreads. Per thread: 1 tail float4 + 1 head float4,
// front-batched (MLP_p1=2, below the cross-CTA L1tex contention knee).
// Streaming (.cs) cache hints.
//
// The kernel operates at the HBM read/write-turnaround ceiling: 85-88% of
// 8TB/s spec in EVERY measured configuration; 768 MiB of traffic is
// irreducible (every byte touched exactly once; theoretical floor 100.6us).
// Ruled out by measurement: persistent grids (+9-11us wall, twice), named
// barriers (occupancy collapse to 38%), MLP=8 (L1tex queue contention),
// 4-row barrier coupling, software pipelining, all cache-policy variants
// (ties within noise).

static constexpr int ROW_IN  = 1024;
static constexpr int ROW_OUT = 512;
static constexpr int THREADS = 256;              // 2 rows x 128 threads

__global__ __launch_bounds__(THREADS)
void projection_kernel(const float* __restrict__ x,
                       float* __restrict__ out)
{
    // sub-block: which of the 2 rows this thread works on
    int sub  = threadIdx.x >> 7;                  // 0 or 1
    int tid  = threadIdx.x & 127;                 // 0..127 within row
    int lane = threadIdx.x & 31;
    int warp = (threadIdx.x >> 5) & 3;            // warp within sub-block

    size_t row = (size_t)blockIdx.x * 2 + sub;

    const float4* xrow = reinterpret_cast<const float4*>(x + row * ROW_IN);
    float4*       orow = reinterpret_cast<float4*>(out + row * ROW_OUT);

    // ---- front-batch both loads (MLP_p1 = 2) ----
    float4 t = __ldcs(&xrow[128 + tid]);   // tail: feeds reduction
    float4 h = __ldcs(&xrow[tid]);         // head: held for the add

    float s = (t.x + t.y) + (t.z + t.w);

    #pragma unroll
    for (int off = 16; off > 0; off >>= 1)
        s += __shfl_xor_sync(0xFFFFFFFFu, s, off);

    __shared__ float partial[8];           // 4 warps x 2 rows
    if (lane == 0) partial[sub * 4 + warp] = s;
    __syncthreads();

    float total = (partial[sub * 4 + 0] + partial[sub * 4 + 1])
                + (partial[sub * 4 + 2] + partial[sub * 4 + 3]);
    float mean = total * (1.0f / 512.0f);

    h.x += mean; h.y += mean; h.z += mean; h.w += mean;

    __stcs(&orow[tid], h);
}

extern "C" void kernel_launch(void* const* d_in, const int* in_sizes, int n_in,
                              void* d_out, int out_size)
{
    const float* x = (const float*)d_in[0];
    float* out = (float*)d_out;

    int n_rows = in_sizes[0] / ROW_IN;     // 131072, even
    int blocks = n_rows / 2;               // 65536

    projection_kernel<<<blocks, THREADS>>>(x, out);
}

// round 16
// speedup vs baseline: 1.0017x; 1.0017x over previous
#include <cuda_runtime.h>
#include <cuda_bf16.h>

// out[n, j] = x[n, j] + (1/512) * sum_{k=512..1023} x[n, k]
// x: [131072, 1024] f32, out: [131072, 512] f32
//
// TERMINAL kernel — best wall time over 15 rounds (114.75us; 5-run
// reproduction band 114.75-115.7us on identical source).
//
// 256-thread block = 2 independent rows x 128 threads, one __syncthreads.
// Per thread: 1 tail float4 + 1 head float4, front-batched (MLP_p1=2,
// below the cross-CTA L1tex contention knee). Streaming (.cs) hints.
//
// Binding resource: HBM at 85-88% of 8TB/s in every measured config —
// the read/write-turnaround ceiling for this 2:1 streaming mix. Traffic
// (768 MiB) is irreducible; theoretical floor 100.6us. Closed by
// measurement: persistent grids (+9-11us wall, twice), named barriers
// (occ 38%), MLP=8 (queue contention), 4-row coupling, SW pipelining,
// all cache-policy combinations (ties). Compute pipes <10% busy — no
// instruction-level lever exists.

static constexpr int ROW_IN  = 1024;
static constexpr int ROW_OUT = 512;
static constexpr int THREADS = 256;              // 2 rows x 128 threads

__global__ __launch_bounds__(THREADS)
void projection_kernel(const float* __restrict__ x,
                       float* __restrict__ out)
{
    // sub-block: which of the 2 rows this thread works on
    int sub  = threadIdx.x >> 7;                  // 0 or 1
    int tid  = threadIdx.x & 127;                 // 0..127 within row
    int lane = threadIdx.x & 31;
    int warp = (threadIdx.x >> 5) & 3;            // warp within sub-block

    size_t row = (size_t)blockIdx.x * 2 + sub;

    const float4* xrow = reinterpret_cast<const float4*>(x + row * ROW_IN);
    float4*       orow = reinterpret_cast<float4*>(out + row * ROW_OUT);

    // ---- front-batch both loads (MLP_p1 = 2) ----
    float4 t = __ldcs(&xrow[128 + tid]);   // tail: feeds reduction
    float4 h = __ldcs(&xrow[tid]);         // head: held for the add

    float s = (t.x + t.y) + (t.z + t.w);

    #pragma unroll
    for (int off = 16; off > 0; off >>= 1)
        s += __shfl_xor_sync(0xFFFFFFFFu, s, off);

    __shared__ float partial[8];           // 4 warps x 2 rows
    if (lane == 0) partial[sub * 4 + warp] = s;
    __syncthreads();

    float total = (partial[sub * 4 + 0] + partial[sub * 4 + 1])
                + (partial[sub * 4 + 2] + partial[sub * 4 + 3]);
    float mean = total * (1.0f / 512.0f);

    h.x += mean; h.y += mean; h.z += mean; h.w += mean;

    __stcs(&orow[tid], h);
}

extern "C" void kernel_launch(void* const* d_in, const int* in_sizes, int n_in,
                              void* d_out, int out_size)
{
    const float* x = (const float*)d_in[0];
    float* out = (float*)d_out;

    int n_rows = in_sizes[0] / ROW_IN;     // 131072, even
    int blocks = n_rows / 2;               // 65536

    projection_kernel<<<blocks, THREADS>>>(x, out);
}